// round 7
// baseline (speedup 1.0000x reference)
#include <cuda_runtime.h>
#include <cuda_fp16.h>

#define NNODES 50000
#define NREL   8
#define D      128
#define NSEG   (NREL * NNODES)      // 400000
#define MAXE   1700000
#define ROWS   128                  // output rows per block
#define NTHR   512
#define ESH    4096                 // staged edge-index window (ints)

// -------- scratch (device globals; no allocation allowed) --------
__device__ int    g_deg[NSEG];
__device__ int    g_off[NSEG + 1];
__device__ int    g_cur[NSEG];
__device__ int    g_bsum[512];
__device__ int    g_sorted[MAXE];
__device__ int    g_st_ei;           // words/elem of edge_index (1=int32, 2=int64)
__device__ int    g_st_et;
__device__ __half g_wh[(NREL + 1) * D * D];   // fp16 [W_0..W_7, root], [out][in]
__device__ __half g_xh[(size_t)NNODES * D];   // fp16 copy of x

// -------- merged setup --------
__global__ void k_prep(const float* __restrict__ W, const float* __restrict__ root,
                       const float* __restrict__ x, int n,
                       const int* __restrict__ ei_w, const int* __restrict__ et_w) {
    int i = blockIdx.x * blockDim.x + threadIdx.x;
    int stride = gridDim.x * blockDim.x;
    if (i == 0) {
        bool e64 = true, t64 = true;
        #pragma unroll
        for (int j = 1; j < 64; j += 2) {
            e64 = e64 && (ei_w[j] == 0);
            t64 = t64 && (et_w[j] == 0);
        }
        g_st_ei = e64 ? 2 : 1;
        g_st_et = t64 ? 2 : 1;
    }
    for (int j = i; j < NSEG; j += stride) g_deg[j] = 0;
    const int nw = NREL * D * D;
    for (int j = i; j < nw + D * D; j += stride)
        g_wh[j] = __float2half(j < nw ? W[j] : root[j - nw]);
    int nx4 = n * D / 4;
    for (int j = i; j < nx4; j += stride) {
        float4 v = __ldg((const float4*)x + j);
        __half2* o = (__half2*)(g_xh + (size_t)j * 4);
        o[0] = __floats2half2_rn(v.x, v.y);
        o[1] = __floats2half2_rn(v.z, v.w);
    }
}

__global__ void k_hist(const int* __restrict__ ei_w, const int* __restrict__ et_w, int E) {
    int i = blockIdx.x * blockDim.x + threadIdx.x;
    if (i < E) {
        int st = g_st_ei, stt = g_st_et;
        int s = ei_w[(size_t)i * st];
        int t = et_w[(size_t)i * stt];
        int key = t * NNODES + s;
        if ((unsigned)key < NSEG) atomicAdd(&g_deg[key], 1);
    }
}

__global__ void k_scan1(int n) {
    __shared__ int sh[1024];
    int tid = threadIdx.x;
    int i = blockIdx.x * 1024 + tid;
    int v = (i < n) ? g_deg[i] : 0;
    sh[tid] = v;
    __syncthreads();
    #pragma unroll
    for (int off = 1; off < 1024; off <<= 1) {
        int t = (tid >= off) ? sh[tid - off] : 0;
        __syncthreads();
        sh[tid] += t;
        __syncthreads();
    }
    if (i < n) g_off[i] = sh[tid] - v;
    if (tid == 1023) g_bsum[blockIdx.x] = sh[1023];
}

__global__ void k_scan2(int nb) {
    __shared__ int sh[512];
    int tid = threadIdx.x;
    int v = (tid < nb) ? g_bsum[tid] : 0;
    sh[tid] = v;
    __syncthreads();
    #pragma unroll
    for (int off = 1; off < 512; off <<= 1) {
        int t = (tid >= off) ? sh[tid - off] : 0;
        __syncthreads();
        sh[tid] += t;
        __syncthreads();
    }
    if (tid < nb) g_bsum[tid] = sh[tid] - v;
}

__global__ void k_scan3(int n, int E) {
    int i = blockIdx.x * blockDim.x + threadIdx.x;
    if (i < n) {
        int o = g_off[i] + g_bsum[i >> 10];
        g_off[i] = o;
        g_cur[i] = o;
    }
    if (i == 0) g_off[n] = E;
}

__global__ void k_scatter(const int* __restrict__ ei_w, const int* __restrict__ et_w, int E) {
    int i = blockIdx.x * blockDim.x + threadIdx.x;
    if (i < E) {
        int st = g_st_ei, stt = g_st_et;
        int s = ei_w[(size_t)i * st];
        int d = ei_w[((size_t)E + i) * st];
        int t = et_w[(size_t)i * stt];
        int key = t * NNODES + s;
        if ((unsigned)key < NSEG) {
            int pos = atomicAdd(&g_cur[key], 1);
            if ((unsigned)pos < MAXE) g_sorted[pos] = d;
        }
    }
}

// -------- fused gather-mean + fp16 MMA GEMM --------
__device__ __forceinline__ void mma_f16(float* c,
                                        unsigned a0, unsigned a1, unsigned a2, unsigned a3,
                                        unsigned b0, unsigned b1) {
    asm volatile(
        "mma.sync.aligned.m16n8k16.row.col.f32.f16.f16.f32 "
        "{%0,%1,%2,%3},{%4,%5,%6,%7},{%8,%9},{%0,%1,%2,%3};"
        : "+f"(c[0]), "+f"(c[1]), "+f"(c[2]), "+f"(c[3])
        : "r"(a0), "r"(a1), "r"(a2), "r"(a3), "r"(b0), "r"(b1));
}

__device__ __forceinline__ void acc_h8(float* a, uint4 u) {
    float2 f0 = __half22float2(*(__half2*)&u.x);
    float2 f1 = __half22float2(*(__half2*)&u.y);
    float2 f2 = __half22float2(*(__half2*)&u.z);
    float2 f3 = __half22float2(*(__half2*)&u.w);
    a[0] += f0.x; a[1] += f0.y; a[2] += f1.x; a[3] += f1.y;
    a[4] += f2.x; a[5] += f2.y; a[6] += f3.x; a[7] += f3.y;
}

__global__ void __launch_bounds__(NTHR)
k_fused(const float* __restrict__ bias, float* __restrict__ out, int n) {
    extern __shared__ char smem[];
    __half (*As)[D + 8] = (__half(*)[D + 8])smem;                     // 34816 B
    __half (*Bs)[D + 8] = (__half(*)[D + 8])(smem + 34816);          // 34816 B
    int* esh = (int*)(smem + 69632);                                  // 16384 B
    int* osh = (int*)(smem + 86016);                                  // 516 B

    int tid  = threadIdx.x;
    int lane = tid & 31;
    int warp = tid >> 5;                 // 0..15
    int hw   = lane >> 4;                // half-warp id
    int hl   = lane & 15;
    int rsub = warp * 2 + hw;            // 0..31
    int rowBase = blockIdx.x * ROWS;
    int gpr = lane >> 2;
    int tg  = lane & 3;
    int rowStrip = (warp & 7) * 16;
    int colBase  = (warp >> 3) * 64;

    float acc[8][4];
    #pragma unroll
    for (int t = 0; t < 8; t++)
        #pragma unroll
        for (int q = 0; q < 4; q++) acc[t][q] = 0.f;

    #pragma unroll 1
    for (int s = 0; s < NREL + 1; s++) {
        __syncthreads();   // prev MMA + esh reads done

        // ---- stage B tile ----
        const __half* Bg = g_wh + (size_t)s * D * D;
        #pragma unroll
        for (int i = 0; i < (D * D / 8) / NTHR; i++) {
            int idx = i * NTHR + tid;
            int o = idx >> 4, c = (idx & 15) * 8;
            *(uint4*)&Bs[o][c] = *(const uint4*)&Bg[o * D + c];
        }

        if (s < NREL) {
            // ---- stage segment offsets (contiguous for this rel) ----
            int seg0 = s * NNODES + rowBase;
            if (tid <= ROWS) {
                int gi = seg0 + tid;
                osh[tid] = g_off[gi > NSEG ? NSEG : gi];
            }
            __syncthreads();

            int base  = osh[0];
            int total = osh[ROWS] - base;

            float a[4][8];
            #pragma unroll
            for (int p = 0; p < 4; p++)
                #pragma unroll
                for (int q = 0; q < 8; q++) a[p][q] = 0.f;

            // ---- chunked: coalesce indices into smem, then gather ----
            for (int c0 = 0; c0 < total; c0 += ESH) {
                int c1 = min(c0 + ESH, total);
                for (int k = c0 + tid; k < c1; k += NTHR)
                    esh[k - c0] = g_sorted[base + k];
                __syncthreads();

                #pragma unroll
                for (int p = 0; p < 4; p++) {
                    int i = p * 32 + rsub;
                    int lo = max(osh[i] - base, c0);
                    int hi = min(osh[i + 1] - base, c1);
                    int j = lo;
                    for (; j + 3 < hi; j += 4) {
                        int d0 = esh[j - c0];
                        int d1 = esh[j - c0 + 1];
                        int d2 = esh[j - c0 + 2];
                        int d3 = esh[j - c0 + 3];
                        uint4 u0 = __ldg((const uint4*)(g_xh + (size_t)d0 * D) + hl);
                        uint4 u1 = __ldg((const uint4*)(g_xh + (size_t)d1 * D) + hl);
                        uint4 u2 = __ldg((const uint4*)(g_xh + (size_t)d2 * D) + hl);
                        uint4 u3 = __ldg((const uint4*)(g_xh + (size_t)d3 * D) + hl);
                        acc_h8(a[p], u0); acc_h8(a[p], u1);
                        acc_h8(a[p], u2); acc_h8(a[p], u3);
                    }
                    for (; j < hi; j++) {
                        int d0 = esh[j - c0];
                        uint4 u0 = __ldg((const uint4*)(g_xh + (size_t)d0 * D) + hl);
                        acc_h8(a[p], u0);
                    }
                }
                __syncthreads();   // esh safe to overwrite
            }

            // ---- normalize + write As ----
            #pragma unroll
            for (int p = 0; p < 4; p++) {
                int i = p * 32 + rsub;
                int cnt = osh[i + 1] - osh[i];
                float inv = (cnt > 0 && rowBase + i < n) ? 1.0f / (float)cnt : 0.0f;
                uint4 pk;
                ((__half2*)&pk)[0] = __floats2half2_rn(a[p][0] * inv, a[p][1] * inv);
                ((__half2*)&pk)[1] = __floats2half2_rn(a[p][2] * inv, a[p][3] * inv);
                ((__half2*)&pk)[2] = __floats2half2_rn(a[p][4] * inv, a[p][5] * inv);
                ((__half2*)&pk)[3] = __floats2half2_rn(a[p][6] * inv, a[p][7] * inv);
                *(uint4*)&As[i][hl * 8] = pk;
            }
        } else {
            #pragma unroll 1
            for (int p = 0; p < 4; p++) {
                int i = p * 32 + rsub;
                int node = rowBase + i;
                uint4 u = make_uint4(0u, 0u, 0u, 0u);
                if (node < n)
                    u = __ldg((const uint4*)(g_xh + (size_t)node * D) + hl);
                *(uint4*)&As[i][hl * 8] = u;
            }
        }
        __syncthreads();

        // ---- MMA over this K=128 slab ----
        #pragma unroll
        for (int kk = 0; kk < 8; kk++) {
            int kb = kk * 16;
            unsigned a0 = *(unsigned*)&As[rowStrip + gpr    ][kb + tg * 2];
            unsigned a1 = *(unsigned*)&As[rowStrip + gpr + 8][kb + tg * 2];
            unsigned a2 = *(unsigned*)&As[rowStrip + gpr    ][kb + tg * 2 + 8];
            unsigned a3 = *(unsigned*)&As[rowStrip + gpr + 8][kb + tg * 2 + 8];
            #pragma unroll
            for (int t = 0; t < 8; t++) {
                unsigned b0 = *(unsigned*)&Bs[colBase + t * 8 + gpr][kb + tg * 2];
                unsigned b1 = *(unsigned*)&Bs[colBase + t * 8 + gpr][kb + tg * 2 + 8];
                mma_f16(acc[t], a0, a1, a2, a3, b0, b1);
            }
        }
    }

    // ---- epilogue ----
    #pragma unroll
    for (int t = 0; t < 8; t++) {
        int col = colBase + t * 8 + tg * 2;
        float bv0 = bias[col], bv1 = bias[col + 1];
        int row0 = rowBase + rowStrip + gpr;
        int row1 = row0 + 8;
        if (row0 < n) {
            float2 v = make_float2(acc[t][0] + bv0, acc[t][1] + bv1);
            *(float2*)(out + (size_t)row0 * D + col) = v;
        }
        if (row1 < n) {
            float2 v = make_float2(acc[t][2] + bv0, acc[t][3] + bv1);
            *(float2*)(out + (size_t)row1 * D + col) = v;
        }
    }
}

#define FUSED_SMEM (34816 + 34816 + ESH * 4 + (ROWS + 1) * 4 + 16)

extern "C" void kernel_launch(void* const* d_in, const int* in_sizes, int n_in,
                              void* d_out, int out_size) {
    const float* x    = (const float*)d_in[0];
    const int*   ei_w = (const int*)d_in[1];
    const int*   et_w = (const int*)d_in[2];
    const float* W    = (const float*)d_in[3];
    const float* root = (const float*)d_in[4];
    const float* bias = (const float*)d_in[5];
    float*       out  = (float*)d_out;

    int E = in_sizes[1] / 2;
    int n = in_sizes[0] / D;
    int nb = (NSEG + 1023) / 1024;

    static bool attr_set = false;
    if (!attr_set) {
        cudaFuncSetAttribute(k_fused, cudaFuncAttributeMaxDynamicSharedMemorySize, FUSED_SMEM);
        attr_set = true;
    }

    k_prep   <<<3200, 512>>>(W, root, x, n, ei_w, et_w);
    k_hist   <<<(E + 255) / 256, 256>>>(ei_w, et_w, E);
    k_scan1  <<<nb, 1024>>>(NSEG);
    k_scan2  <<<1, 512>>>(nb);
    k_scan3  <<<(NSEG + 255) / 256, 256>>>(NSEG, E);
    k_scatter<<<(E + 255) / 256, 256>>>(ei_w, et_w, E);
    k_fused  <<<(n + ROWS - 1) / ROWS, NTHR, FUSED_SMEM>>>(bias, out, n);
}